// round 5
// baseline (speedup 1.0000x reference)
#include <cuda_runtime.h>
#include <cstdint>
#include <math.h>

#define BATCH 4
#define SEQ   4096
#define FEAT  1024
#define HID   1024

// ---------------------------------------------------------------------------
// Scratch (device globals — allocation-free per harness rules)
// All MMA k-dims stored sigma-permuted within 8-groups: [0,4,1,5,2,6,3,7]
// ---------------------------------------------------------------------------
__device__ float g_xc [BATCH * SEQ * FEAT];   // x  (tf32, sigma-f)    64 MB
__device__ float g_wqt[FEAT * HID];           // Wq^T (tf32, sigma-f)   4 MB
__device__ float g_wkt[FEAT * HID];           // Wk^T (tf32, sigma-f)   4 MB
__device__ float g_wvt[FEAT * HID];           // Wv^T (tf32, sigma-f)   4 MB
__device__ float g_q  [BATCH * SEQ * HID];    // Q (tf32, sigma-h)     64 MB
__device__ float g_k  [BATCH * SEQ * HID];    // K (tf32, sigma-h)     64 MB
__device__ float g_v  [BATCH * SEQ * HID];    // V (natural h)         64 MB
__device__ float g_vt [BATCH * HID * SEQ];    // V^T (tf32, sigma-s)   64 MB
__device__ float g_p  [(size_t)BATCH * SEQ * SEQ]; // exp(scores)     256 MB
__device__ float g_rs [BATCH * SEQ];          // row sums of exp

// ---------------------------------------------------------------------------
__device__ __forceinline__ float to_tf32(float x) {
    uint32_t u;
    asm("cvt.rn.tf32.f32 %0, %1;" : "=r"(u) : "f"(x));
    return __uint_as_float(u);
}

__device__ __forceinline__ void cp_async16(uint32_t s, const float* g) {
    asm volatile("cp.async.cg.shared.global [%0], [%1], 16;"
                 :: "r"(s), "l"(__cvta_generic_to_global((const void*)g)) : "memory");
}

__device__ __forceinline__ uint32_t smem_u32(const void* p) {
    uint32_t a;
    asm("{ .reg .u64 t; cvta.to.shared.u64 t, %1; cvt.u32.u64 %0, t; }"
        : "=r"(a) : "l"(p));
    return a;
}

__device__ __forceinline__ void mma_tf32(float* c, float2 a01, float2 a23, float2 b) {
    asm volatile(
        "mma.sync.aligned.m16n8k8.row.col.f32.tf32.tf32.f32 "
        "{%0,%1,%2,%3}, {%4,%5,%6,%7}, {%8,%9}, {%0,%1,%2,%3};"
        : "+f"(c[0]), "+f"(c[1]), "+f"(c[2]), "+f"(c[3])
        : "r"(__float_as_uint(a01.x)), "r"(__float_as_uint(a23.x)),
          "r"(__float_as_uint(a01.y)), "r"(__float_as_uint(a23.y)),
          "r"(__float_as_uint(b.x)),   "r"(__float_as_uint(b.y)));
}

// ---------------------------------------------------------------------------
// tf32 mma.sync GEMM (NT), sigma-k layout. BM=128,BN=256,BK=32, 3 stages.
// Epilogue MODE: 0 = bias + tf32-round + sigma-store (Q/K)
//               1 = bias + natural store (V)
//               2 = exp(alpha*acc) + tf32-round + sigma-store + rowsum (scores)
//               3 = acc / rowsum, natural store (output)
// ---------------------------------------------------------------------------
#define GBM 128
#define GBN 256
#define GBK 32
#define GST 3
#define AST 40
#define A_FLTS (GBM * AST)
#define B_FLTS (GBN * AST)
#define STAGE_FLTS (A_FLTS + B_FLTS)
#define GEMM_SMEM (GST * STAGE_FLTS * 4)

template <int MODE>
__global__ __launch_bounds__(256, 1)
void gemm_mma(const float* __restrict__ A, const float* __restrict__ B,
              const float* __restrict__ bias, float* __restrict__ C,
              float* __restrict__ rowsum,
              int K, int ldc, float alpha,
              long long sA, long long sB, long long sC)
{
    extern __shared__ float sm[];
    const uint32_t sbase = smem_u32(sm);

    const int tid = threadIdx.x;
    const int wid = tid >> 5, lane = tid & 31;
    const int g = lane >> 2, t = lane & 3;
    const int wm = wid >> 2, wn = wid & 3;
    const int wm0 = wm * 64, wn0 = wn * 64;

    const int bz = blockIdx.z;
    A += sA * bz; B += sB * bz; C += sC * bz;
    if (MODE == 2 || MODE == 3) rowsum += (long long)SEQ * bz;   // per-batch rowsums
    const int m0 = blockIdx.y * GBM;
    const int n0 = blockIdx.x * GBN;

    const int NITER = K / GBK;

    auto load_stage = [&](int c) {
        const int slot = c % GST;
        const uint32_t s_a = sbase + slot * STAGE_FLTS * 4;
        const uint32_t s_b = s_a + A_FLTS * 4;
        const long long koff = (long long)c * GBK;
        #pragma unroll
        for (int i = 0; i < 4; i++) {
            int s = tid + i * 256;
            int row = s >> 3, ch = s & 7;
            cp_async16(s_a + (uint32_t)(row * AST + ch * 4) * 4,
                       A + (long long)(m0 + row) * K + koff + ch * 4);
        }
        #pragma unroll
        for (int i = 0; i < 8; i++) {
            int s = tid + i * 256;
            int row = s >> 3, ch = s & 7;
            cp_async16(s_b + (uint32_t)(row * AST + ch * 4) * 4,
                       B + (long long)(n0 + row) * K + koff + ch * 4);
        }
        asm volatile("cp.async.commit_group;" ::: "memory");
    };

    float acc[4][8][4];
    #pragma unroll
    for (int mi = 0; mi < 4; mi++)
        #pragma unroll
        for (int ni = 0; ni < 8; ni++)
            #pragma unroll
            for (int r = 0; r < 4; r++) acc[mi][ni][r] = 0.f;

    load_stage(0);
    if (NITER > 1) load_stage(1);

    for (int it = 0; it < NITER; it++) {
        if (it < NITER - 1)
            asm volatile("cp.async.wait_group 1;" ::: "memory");
        else
            asm volatile("cp.async.wait_group 0;" ::: "memory");
        __syncthreads();

        if (it + 2 < NITER) load_stage(it + 2);

        const int slot = it % GST;
        const float* as = sm + slot * STAGE_FLTS + wm0 * AST;
        const float* bs = sm + slot * STAGE_FLTS + A_FLTS + wn0 * AST;

        #pragma unroll
        for (int kk = 0; kk < 4; kk++) {
            const int kc = kk * 8 + 2 * t;          // sigma layout: (t, t+4) adjacent
            float2 a2[4][2];
            #pragma unroll
            for (int mi = 0; mi < 4; mi++) {
                const float* ap = as + (mi * 16 + g) * AST + kc;
                a2[mi][0] = *(const float2*)ap;              // rows g    -> a0, a2
                a2[mi][1] = *(const float2*)(ap + 8 * AST);  // rows g+8  -> a1, a3
            }
            float2 b2[8];
            #pragma unroll
            for (int ni = 0; ni < 8; ni++)
                b2[ni] = *(const float2*)(bs + (ni * 8 + g) * AST + kc);
            #pragma unroll
            for (int mi = 0; mi < 4; mi++)
                #pragma unroll
                for (int ni = 0; ni < 8; ni++)
                    mma_tf32(acc[mi][ni], a2[mi][0], a2[mi][1], b2[ni]);
        }
    }

    // ---------------- epilogue ----------------
    // sigma positions for logical cols (2t, 2t+1) within an 8-group:
    const int p0 = (t < 2) ? 4 * t : 4 * t - 7;   // logical 2t
    const int p1 = p0 + 2;                         // logical 2t+1

    if (MODE == 3) {
        #pragma unroll
        for (int mi = 0; mi < 4; mi++) {
            const int row0 = m0 + wm0 + mi * 16 + g;
            const float i0 = 1.0f / rowsum[row0];
            const float i8 = 1.0f / rowsum[row0 + 8];
            #pragma unroll
            for (int ni = 0; ni < 8; ni++) {
                const int col = n0 + wn0 + ni * 8 + 2 * t;
                *(float2*)(C + (long long)row0 * ldc + col) =
                    make_float2(acc[mi][ni][0] * i0, acc[mi][ni][1] * i0);
                *(float2*)(C + (long long)(row0 + 8) * ldc + col) =
                    make_float2(acc[mi][ni][2] * i8, acc[mi][ni][3] * i8);
            }
        }
    } else if (MODE == 2) {
        #pragma unroll
        for (int mi = 0; mi < 4; mi++) {
            const int row0 = m0 + wm0 + mi * 16 + g;
            float s0 = 0.f, s8 = 0.f;
            #pragma unroll
            for (int ni = 0; ni < 8; ni++) {
                const int ng = n0 + wn0 + ni * 8;
                float e0 = to_tf32(__expf(alpha * acc[mi][ni][0]));
                float e1 = to_tf32(__expf(alpha * acc[mi][ni][1]));
                float e2 = to_tf32(__expf(alpha * acc[mi][ni][2]));
                float e3 = to_tf32(__expf(alpha * acc[mi][ni][3]));
                s0 += e0 + e1;  s8 += e2 + e3;
                float* r0p = C + (long long)row0 * ldc + ng;
                float* r8p = C + (long long)(row0 + 8) * ldc + ng;
                r0p[p0] = e0;  r0p[p1] = e1;
                r8p[p0] = e2;  r8p[p1] = e3;
            }
            s0 += __shfl_xor_sync(0xffffffffu, s0, 1);
            s0 += __shfl_xor_sync(0xffffffffu, s0, 2);
            s8 += __shfl_xor_sync(0xffffffffu, s8, 1);
            s8 += __shfl_xor_sync(0xffffffffu, s8, 2);
            if (t == 0) {
                atomicAdd(&rowsum[row0], s0);
                atomicAdd(&rowsum[row0 + 8], s8);
            }
        }
    } else {
        #pragma unroll
        for (int mi = 0; mi < 4; mi++) {
            const int row0 = m0 + wm0 + mi * 16 + g;
            #pragma unroll
            for (int ni = 0; ni < 8; ni++) {
                const int ng = n0 + wn0 + ni * 8;
                const float2 bv = *(const float2*)(bias + ng + 2 * t);
                float v0 = acc[mi][ni][0] + bv.x;
                float v1 = acc[mi][ni][1] + bv.y;
                float v2 = acc[mi][ni][2] + bv.x;
                float v3 = acc[mi][ni][3] + bv.y;
                if (MODE == 0) {
                    v0 = to_tf32(v0); v1 = to_tf32(v1);
                    v2 = to_tf32(v2); v3 = to_tf32(v3);
                    float* r0p = C + (long long)row0 * ldc + ng;
                    float* r8p = C + (long long)(row0 + 8) * ldc + ng;
                    r0p[p0] = v0;  r0p[p1] = v1;
                    r8p[p0] = v2;  r8p[p1] = v3;
                } else {
                    const int col = ng + 2 * t;
                    *(float2*)(C + (long long)row0 * ldc + col) = make_float2(v0, v1);
                    *(float2*)(C + (long long)(row0 + 8) * ldc + col) = make_float2(v2, v3);
                }
            }
        }
    }
}

// ---------------------------------------------------------------------------
// x -> tf32 + sigma-permute k within 8-groups: mem order [0,4,1,5,2,6,3,7]
// ---------------------------------------------------------------------------
__global__ __launch_bounds__(256)
void convert_sigma_kernel(const float4* __restrict__ in, float4* __restrict__ out, int n8)
{
    int i = blockIdx.x * 256 + threadIdx.x;
    if (i < n8) {
        float4 v0 = in[i * 2], v1 = in[i * 2 + 1];
        float4 o0 = make_float4(to_tf32(v0.x), to_tf32(v1.x), to_tf32(v0.y), to_tf32(v1.y));
        float4 o1 = make_float4(to_tf32(v0.z), to_tf32(v1.z), to_tf32(v0.w), to_tf32(v1.w));
        out[i * 2] = o0;
        out[i * 2 + 1] = o1;
    }
}

// ---------------------------------------------------------------------------
// Transpose + tf32 round + sigma-permute the (output-row-index = k) dim.
// in [R x Cc], out [Cc x R] with out[c][sigp(r)] = tf32(in[r][c])
// ---------------------------------------------------------------------------
__global__ __launch_bounds__(256)
void transpose_sigma(const float* __restrict__ in, float* __restrict__ out,
                     int R, int Cc, long long sIn, long long sOut)
{
    __shared__ float tbuf[32][33];
    const int bz = blockIdx.z;
    in += sIn * bz; out += sOut * bz;
    const int c0 = blockIdx.x * 32, r0 = blockIdx.y * 32;
    const int x = threadIdx.x, y = threadIdx.y;   // (32, 8)
    #pragma unroll
    for (int i = 0; i < 32; i += 8)
        tbuf[y + i][x] = in[(long long)(r0 + y + i) * Cc + c0 + x];
    __syncthreads();
    const int j = x & 7;
    const int sx = (x & ~7) | ((j < 4) ? (2 * j) : (2 * (j - 4) + 1));
    #pragma unroll
    for (int i = 0; i < 32; i += 8)
        out[(long long)(c0 + y + i) * R + r0 + sx] = to_tf32(tbuf[x][y + i]);
}

__global__ __launch_bounds__(256)
void zero_kernel(float* __restrict__ p, int n)
{
    int i = blockIdx.x * 256 + threadIdx.x;
    if (i < n) p[i] = 0.f;
}

// ---------------------------------------------------------------------------
extern "C" void kernel_launch(void* const* d_in, const int* in_sizes, int n_in,
                              void* d_out, int out_size)
{
    const float* x  = (const float*)d_in[0];
    const float* Wq = (const float*)d_in[1];
    const float* bq = (const float*)d_in[2];
    const float* Wk = (const float*)d_in[3];
    const float* bk = (const float*)d_in[4];
    const float* Wv = (const float*)d_in[5];
    const float* bv = (const float*)d_in[6];
    float* out = (float*)d_out;

    float *xc, *wqt, *wkt, *wvt, *q, *k, *v, *vt, *p, *rs;
    cudaGetSymbolAddress((void**)&xc,  g_xc);
    cudaGetSymbolAddress((void**)&wqt, g_wqt);
    cudaGetSymbolAddress((void**)&wkt, g_wkt);
    cudaGetSymbolAddress((void**)&wvt, g_wvt);
    cudaGetSymbolAddress((void**)&q,   g_q);
    cudaGetSymbolAddress((void**)&k,   g_k);
    cudaGetSymbolAddress((void**)&v,   g_v);
    cudaGetSymbolAddress((void**)&vt,  g_vt);
    cudaGetSymbolAddress((void**)&p,   g_p);
    cudaGetSymbolAddress((void**)&rs,  g_rs);

    cudaFuncSetAttribute(gemm_mma<0>, cudaFuncAttributeMaxDynamicSharedMemorySize, GEMM_SMEM);
    cudaFuncSetAttribute(gemm_mma<1>, cudaFuncAttributeMaxDynamicSharedMemorySize, GEMM_SMEM);
    cudaFuncSetAttribute(gemm_mma<2>, cudaFuncAttributeMaxDynamicSharedMemorySize, GEMM_SMEM);
    cudaFuncSetAttribute(gemm_mma<3>, cudaFuncAttributeMaxDynamicSharedMemorySize, GEMM_SMEM);

    // 0) zero rowsums + convert x (tf32 + sigma)
    zero_kernel<<<(BATCH * SEQ + 255) / 256, 256>>>(rs, BATCH * SEQ);
    convert_sigma_kernel<<<(BATCH * SEQ * FEAT / 8 + 255) / 256, 256>>>(
        (const float4*)x, (float4*)xc, BATCH * SEQ * FEAT / 8);

    // 1) W transposes (tf32 + sigma on f)
    dim3 tw(HID / 32, FEAT / 32, 1);
    transpose_sigma<<<tw, dim3(32, 8)>>>(Wq, wqt, FEAT, HID, 0, 0);
    transpose_sigma<<<tw, dim3(32, 8)>>>(Wk, wkt, FEAT, HID, 0, 0);
    transpose_sigma<<<tw, dim3(32, 8)>>>(Wv, wvt, FEAT, HID, 0, 0);

    // 2) QKV projections
    dim3 gqkv(HID / GBN, (BATCH * SEQ) / GBM, 1);
    gemm_mma<0><<<gqkv, 256, GEMM_SMEM>>>(xc, wqt, bq, q, nullptr, FEAT, HID, 1.0f, 0, 0, 0);
    gemm_mma<0><<<gqkv, 256, GEMM_SMEM>>>(xc, wkt, bk, k, nullptr, FEAT, HID, 1.0f, 0, 0, 0);
    gemm_mma<1><<<gqkv, 256, GEMM_SMEM>>>(xc, wvt, bv, v, nullptr, FEAT, HID, 1.0f, 0, 0, 0);

    // 3) p = exp((Q K^T)/32) (sigma-stored) + rowsums
    dim3 gs(SEQ / GBN, SEQ / GBM, BATCH);
    gemm_mma<2><<<gs, 256, GEMM_SMEM>>>(q, k, nullptr, p, rs, HID, SEQ, 1.0f / 32.0f,
                                        (long long)SEQ * HID, (long long)SEQ * HID,
                                        (long long)SEQ * SEQ);

    // 4) V^T (tf32 + sigma on s)
    dim3 tv(HID / 32, SEQ / 32, BATCH);
    transpose_sigma<<<tv, dim3(32, 8)>>>(v, vt, SEQ, HID,
                                         (long long)SEQ * HID, (long long)HID * SEQ);

    // 5) out = (P V) / rowsum
    dim3 go(HID / GBN, SEQ / GBM, BATCH);
    gemm_mma<3><<<go, 256, GEMM_SMEM>>>(p, vt, nullptr, out, rs, SEQ, HID, 1.0f,
                                        (long long)SEQ * SEQ, (long long)HID * SEQ,
                                        (long long)SEQ * HID);
}